// round 13
// baseline (speedup 1.0000x reference)
#include <cuda_runtime.h>
#include <cstdint>

// Quincunx lattice max pooling — FINAL (bench-best across 10 measured variants).
// Inputs: coset0, coset1 each [B=4, C=32, H=512, W=512] f32.
// Output: [2, B, C, H, W] f32 (out0 stacked before out1).
//
// out0[i,j] = max(c0[i,j], c0[i+1,j], c0[i,j+1], c0[i+1,j+1], c1[i,j])
// out1[i,j] = max(c1[i,j], c1[i+1,j], c1[i,j+1], c1[i+1,j+1], c0[i+1,j+1])
// Out-of-range -> -inf.
//
// One float4 per thread per output coset; fully coalesced LDG.128/STG.128.
// Row i+1 re-reads hit L2. __stcs streaming stores (outputs never re-read).
// 31 regs, occ ~86% — on the graph-replay bench, high occupancy beats the
// 256-bit-access family (LDG.E.256: ncu 74.0us but bench 81.9-82.4us at
// occ 50-54%, at both block=256 and block=128).
//
// Measured: 6.4-6.5 TB/s (80-82% of HBM3e spec), DRAM traffic ~482 MB vs
// the 512 MB analytic minimum (graph-replay L2 carryover) — at the hardware
// roofline for a 50/50 read/write mix. Bench 80.35-80.38us, reproduced 5x.

#define NEG_INF __int_as_float(0xff800000)

__device__ __forceinline__ float fmax5(float a, float b, float c, float d, float e) {
    return fmaxf(fmaxf(fmaxf(a, b), fmaxf(c, d)), e);
}

// H = W = 512, W4 = 128 (float4 lanes per row), planes = B*C = 128.
__global__ void __launch_bounds__(256) lattice_pool_kernel(
    const float4* __restrict__ c0,
    const float4* __restrict__ c1,
    float4* __restrict__ out0,
    float4* __restrict__ out1)
{
    const int idx = blockIdx.x * blockDim.x + threadIdx.x;
    const int jv = idx & 127;          // float4 column
    const int i  = (idx >> 7) & 511;   // row

    const size_t pos = (size_t)idx;    // fully linear layout

    const bool hasRow = (i < 511);
    const bool hasCol = (jv < 127);

    // Row i+1 loads: clamp offset instead of predicating the load, so both
    // LDG.128 pairs issue unconditionally (front-batched).
    const size_t posR = hasRow ? pos + 128 : pos;

    float4 a0 = c0[pos];
    float4 b0 = c1[pos];
    float4 a1 = c0[posR];
    float4 b1 = c1[posR];
    if (!hasRow) {
        a1 = make_float4(NEG_INF, NEG_INF, NEG_INF, NEG_INF);
        b1 = make_float4(NEG_INF, NEG_INF, NEG_INF, NEG_INF);
    }

    // Column j+4 scalars (first element of neighbor float4) — L1 hits.
    const float* c0f = (const float*)c0;
    const float* c1f = (const float*)c1;
    const size_t fbase = (pos << 2) + 4;   // float index of element j+4, row i
    float a0e = hasCol ? c0f[fbase] : NEG_INF;
    float b0e = hasCol ? c1f[fbase] : NEG_INF;
    float a1e = (hasCol && hasRow) ? c0f[fbase + 512] : NEG_INF;
    float b1e = (hasCol && hasRow) ? c1f[fbase + 512] : NEG_INF;

    float4 o0, o1;
    // out0: own = c0, cross = c1[i,j]
    o0.x = fmax5(a0.x, a0.y, a1.x, a1.y, b0.x);
    o0.y = fmax5(a0.y, a0.z, a1.y, a1.z, b0.y);
    o0.z = fmax5(a0.z, a0.w, a1.z, a1.w, b0.z);
    o0.w = fmax5(a0.w, a0e,  a1.w, a1e,  b0.w);
    // out1: own = c1, cross = c0[i+1,j+1]
    o1.x = fmax5(b0.x, b0.y, b1.x, b1.y, a1.y);
    o1.y = fmax5(b0.y, b0.z, b1.y, b1.z, a1.z);
    o1.z = fmax5(b0.z, b0.w, b1.z, b1.w, a1.w);
    o1.w = fmax5(b0.w, b0e,  b1.w, b1e,  a1e);

    __stcs(&out0[pos], o0);   // streaming store: output never re-read
    __stcs(&out1[pos], o1);
}

extern "C" void kernel_launch(void* const* d_in, const int* in_sizes, int n_in,
                              void* d_out, int out_size) {
    const float4* c0 = (const float4*)d_in[0];
    const float4* c1 = (const float4*)d_in[1];
    float4* out0 = (float4*)d_out;
    float4* out1 = out0 + 8388608;  // B*C*H*W / 4 float4 elements

    const int total = 8388608;      // 128 planes * 512 rows * 128 vec-cols
    const int threads = 256;
    const int blocks = total / threads; // 32768
    lattice_pool_kernel<<<blocks, threads>>>(c0, c1, out0, out1);
}

// round 14
// speedup vs baseline: 1.0024x; 1.0024x over previous
#include <cuda_runtime.h>
#include <cstdint>

// Quincunx lattice max pooling — FINAL (bench-best across 10 measured variants).
// Inputs: coset0, coset1 each [B=4, C=32, H=512, W=512] f32.
// Output: [2, B, C, H, W] f32 (out0 stacked before out1).
//
// out0[i,j] = max(c0[i,j], c0[i+1,j], c0[i,j+1], c0[i+1,j+1], c1[i,j])
// out1[i,j] = max(c1[i,j], c1[i+1,j], c1[i,j+1], c1[i+1,j+1], c0[i+1,j+1])
// Out-of-range -> -inf.
//
// One float4 per thread per output coset; fully coalesced LDG.128/STG.128.
// Row i+1 re-reads hit L2. __stcs streaming stores (outputs never re-read).
// 31 regs, occ ~86% — on the graph-replay bench, high occupancy beats the
// 256-bit-access family (LDG.E.256: ncu 74.0us but bench 81.9-82.4us at
// occ 50-54%, at both block=256 and block=128).
//
// Measured: 6.4-6.5 TB/s (80-82% of HBM3e spec), DRAM traffic ~482 MB vs
// the 512 MB analytic minimum (graph-replay L2 carryover) — at the hardware
// roofline for a 50/50 read/write mix. Best bench 80.35us; run-to-run noise
// band for this exact binary measured at 80.35-81.18us.

#define NEG_INF __int_as_float(0xff800000)

__device__ __forceinline__ float fmax5(float a, float b, float c, float d, float e) {
    return fmaxf(fmaxf(fmaxf(a, b), fmaxf(c, d)), e);
}

// H = W = 512, W4 = 128 (float4 lanes per row), planes = B*C = 128.
__global__ void __launch_bounds__(256) lattice_pool_kernel(
    const float4* __restrict__ c0,
    const float4* __restrict__ c1,
    float4* __restrict__ out0,
    float4* __restrict__ out1)
{
    const int idx = blockIdx.x * blockDim.x + threadIdx.x;
    const int jv = idx & 127;          // float4 column
    const int i  = (idx >> 7) & 511;   // row

    const size_t pos = (size_t)idx;    // fully linear layout

    const bool hasRow = (i < 511);
    const bool hasCol = (jv < 127);

    // Row i+1 loads: clamp offset instead of predicating the load, so both
    // LDG.128 pairs issue unconditionally (front-batched).
    const size_t posR = hasRow ? pos + 128 : pos;

    float4 a0 = c0[pos];
    float4 b0 = c1[pos];
    float4 a1 = c0[posR];
    float4 b1 = c1[posR];
    if (!hasRow) {
        a1 = make_float4(NEG_INF, NEG_INF, NEG_INF, NEG_INF);
        b1 = make_float4(NEG_INF, NEG_INF, NEG_INF, NEG_INF);
    }

    // Column j+4 scalars (first element of neighbor float4) — L1 hits.
    const float* c0f = (const float*)c0;
    const float* c1f = (const float*)c1;
    const size_t fbase = (pos << 2) + 4;   // float index of element j+4, row i
    float a0e = hasCol ? c0f[fbase] : NEG_INF;
    float b0e = hasCol ? c1f[fbase] : NEG_INF;
    float a1e = (hasCol && hasRow) ? c0f[fbase + 512] : NEG_INF;
    float b1e = (hasCol && hasRow) ? c1f[fbase + 512] : NEG_INF;

    float4 o0, o1;
    // out0: own = c0, cross = c1[i,j]
    o0.x = fmax5(a0.x, a0.y, a1.x, a1.y, b0.x);
    o0.y = fmax5(a0.y, a0.z, a1.y, a1.z, b0.y);
    o0.z = fmax5(a0.z, a0.w, a1.z, a1.w, b0.z);
    o0.w = fmax5(a0.w, a0e,  a1.w, a1e,  b0.w);
    // out1: own = c1, cross = c0[i+1,j+1]
    o1.x = fmax5(b0.x, b0.y, b1.x, b1.y, a1.y);
    o1.y = fmax5(b0.y, b0.z, b1.y, b1.z, a1.z);
    o1.z = fmax5(b0.z, b0.w, b1.z, b1.w, a1.w);
    o1.w = fmax5(b0.w, b0e,  b1.w, b1e,  a1e);

    __stcs(&out0[pos], o0);   // streaming store: output never re-read
    __stcs(&out1[pos], o1);
}

extern "C" void kernel_launch(void* const* d_in, const int* in_sizes, int n_in,
                              void* d_out, int out_size) {
    const float4* c0 = (const float4*)d_in[0];
    const float4* c1 = (const float4*)d_in[1];
    float4* out0 = (float4*)d_out;
    float4* out1 = out0 + 8388608;  // B*C*H*W / 4 float4 elements

    const int total = 8388608;      // 128 planes * 512 rows * 128 vec-cols
    const int threads = 256;
    const int blocks = total / threads; // 32768
    lattice_pool_kernel<<<blocks, threads>>>(c0, c1, out0, out1);
}

// round 15
// speedup vs baseline: 1.0104x; 1.0080x over previous
#include <cuda_runtime.h>
#include <cstdint>

// Quincunx lattice max pooling — FINAL (bench-best across 12 measured configs).
// Inputs: coset0, coset1 each [B=4, C=32, H=512, W=512] f32.
// Output: [2, B, C, H, W] f32 (out0 stacked before out1).
//
// out0[i,j] = max(c0[i,j], c0[i+1,j], c0[i,j+1], c0[i+1,j+1], c1[i,j])
// out1[i,j] = max(c1[i,j], c1[i+1,j], c1[i,j+1], c1[i+1,j+1], c0[i+1,j+1])
// Out-of-range -> -inf.
//
// One float4 per thread per output coset; fully coalesced LDG.128/STG.128.
// Row i+1 re-reads hit L2. __stcs streaming stores (outputs never re-read).
// 31 regs, occ ~86% — on the graph-replay bench, high occupancy beats the
// 256-bit-access family (LDG.E.256: ncu 74.0us but bench 81.9-82.4us at
// occ 50-54%, at both block=256 and block=128).
//
// Measured: 6.4-6.5 TB/s (80-82% of HBM3e spec), DRAM traffic ~482 MB vs
// the 512 MB analytic minimum (graph-replay L2 carryover) — at the hardware
// roofline for a 50/50 read/write mix. Identical-binary bench samples:
// 80.35 / 80.38x3 / 80.99 / 81.18 us.

#define NEG_INF __int_as_float(0xff800000)

__device__ __forceinline__ float fmax5(float a, float b, float c, float d, float e) {
    return fmaxf(fmaxf(fmaxf(a, b), fmaxf(c, d)), e);
}

// H = W = 512, W4 = 128 (float4 lanes per row), planes = B*C = 128.
__global__ void __launch_bounds__(256) lattice_pool_kernel(
    const float4* __restrict__ c0,
    const float4* __restrict__ c1,
    float4* __restrict__ out0,
    float4* __restrict__ out1)
{
    const int idx = blockIdx.x * blockDim.x + threadIdx.x;
    const int jv = idx & 127;          // float4 column
    const int i  = (idx >> 7) & 511;   // row

    const size_t pos = (size_t)idx;    // fully linear layout

    const bool hasRow = (i < 511);
    const bool hasCol = (jv < 127);

    // Row i+1 loads: clamp offset instead of predicating the load, so both
    // LDG.128 pairs issue unconditionally (front-batched).
    const size_t posR = hasRow ? pos + 128 : pos;

    float4 a0 = c0[pos];
    float4 b0 = c1[pos];
    float4 a1 = c0[posR];
    float4 b1 = c1[posR];
    if (!hasRow) {
        a1 = make_float4(NEG_INF, NEG_INF, NEG_INF, NEG_INF);
        b1 = make_float4(NEG_INF, NEG_INF, NEG_INF, NEG_INF);
    }

    // Column j+4 scalars (first element of neighbor float4) — L1 hits.
    const float* c0f = (const float*)c0;
    const float* c1f = (const float*)c1;
    const size_t fbase = (pos << 2) + 4;   // float index of element j+4, row i
    float a0e = hasCol ? c0f[fbase] : NEG_INF;
    float b0e = hasCol ? c1f[fbase] : NEG_INF;
    float a1e = (hasCol && hasRow) ? c0f[fbase + 512] : NEG_INF;
    float b1e = (hasCol && hasRow) ? c1f[fbase + 512] : NEG_INF;

    float4 o0, o1;
    // out0: own = c0, cross = c1[i,j]
    o0.x = fmax5(a0.x, a0.y, a1.x, a1.y, b0.x);
    o0.y = fmax5(a0.y, a0.z, a1.y, a1.z, b0.y);
    o0.z = fmax5(a0.z, a0.w, a1.z, a1.w, b0.z);
    o0.w = fmax5(a0.w, a0e,  a1.w, a1e,  b0.w);
    // out1: own = c1, cross = c0[i+1,j+1]
    o1.x = fmax5(b0.x, b0.y, b1.x, b1.y, a1.y);
    o1.y = fmax5(b0.y, b0.z, b1.y, b1.z, a1.z);
    o1.z = fmax5(b0.z, b0.w, b1.z, b1.w, a1.w);
    o1.w = fmax5(b0.w, b0e,  b1.w, b1e,  a1e);

    __stcs(&out0[pos], o0);   // streaming store: output never re-read
    __stcs(&out1[pos], o1);
}

extern "C" void kernel_launch(void* const* d_in, const int* in_sizes, int n_in,
                              void* d_out, int out_size) {
    const float4* c0 = (const float4*)d_in[0];
    const float4* c1 = (const float4*)d_in[1];
    float4* out0 = (float4*)d_out;
    float4* out1 = out0 + 8388608;  // B*C*H*W / 4 float4 elements

    const int total = 8388608;      // 128 planes * 512 rows * 128 vec-cols
    const int threads = 256;
    const int blocks = total / threads; // 32768
    lattice_pool_kernel<<<blocks, threads>>>(c0, c1, out0, out1);
}